// round 4
// baseline (speedup 1.0000x reference)
#include <cuda_runtime.h>

#define BATCH 16
#define CH    256
#define HH    64
#define WW    64
#define NPIX  (HH * WW)

typedef unsigned long long u64;

// ---- packed f32x2 helpers (Blackwell FFMA2, PTX-only) ----
__device__ __forceinline__ u64 pk2(float lo, float hi) {
    u64 r;
    asm("mov.b64 %0, {%1, %2};" : "=l"(r) : "f"(lo), "f"(hi));
    return r;
}
__device__ __forceinline__ void upk2(u64 v, float &lo, float &hi) {
    asm("mov.b64 {%0, %1}, %2;" : "=f"(lo), "=f"(hi) : "l"(v));
}
__device__ __forceinline__ void ffma2(u64 &d, u64 a, u64 b) {
    asm("fma.rn.f32x2 %0, %1, %2, %0;" : "+l"(d) : "l"(a), "l"(b));
}

// out[b, oi*9+oj, i, j] = (1/C) * sum_c x[b,c,i,j] * y[b,c,i+oi-4, j+oj-4]
// Thread: 8 consecutive j (one group), one oi, all 9 oj.
// Parity accumulator packing (zero y re-pack MOVs, 3 x re-packs):
//   even oj: pixel pairs (0,1)(2,3)(4,5)(6,7)
//   odd  oj: pixel pairs (1,2)(3,4)(5,6) + scalar pixels 0 and 7
// Block: 8 tx * 9 oi * 2 rows = 144 threads.
// 4 blocks/SM (112-reg budget) -> 18 warps/SM; grid 512 <= 4*148 -> single wave.
__global__ __launch_bounds__(144, 4)
void corr_kernel(const float* __restrict__ x, const float* __restrict__ y,
                 float* __restrict__ out) {
    const int tid = threadIdx.x;
    const int tx  = tid & 7;          // j-group 0..7
    const int oi  = (tid >> 3) % 9;   // row displacement 0..8
    const int ty  = tid / 72;         // row within block 0..1
    const int b   = blockIdx.y;
    const int i   = blockIdx.x * 2 + ty;
    const int j0  = tx * 8;
    const int r   = i + oi - 4;       // displaced y row

    float* outp = out + (((size_t)b * 81 + (size_t)oi * 9) * HH + i) * WW + j0;

    if ((unsigned)r >= (unsigned)HH) {   // whole displaced row OOB -> zeros
        const float4 z = make_float4(0.f, 0.f, 0.f, 0.f);
        #pragma unroll
        for (int oj = 0; oj < 9; ++oj) {
            *(float4*)(outp + oj * NPIX)     = z;
            *(float4*)(outp + oj * NPIX + 4) = z;
        }
        return;
    }

    const float* xp = x + (size_t)b * CH * NPIX + i * WW + j0;
    const float* yp = y + (size_t)b * CH * NPIX + r * WW + (j0 - 4);
    const bool first = (tx == 0);   // window cols -4..-1 invalid
    const bool last  = (tx == 7);   // window cols 64..67 invalid

    // Accumulators
    u64   ae[5][4];   // even oj=2e: pairs (2p,2p+1)
    u64   ao[4][3];   // odd  oj=2o+1: pairs (2p+1,2p+2)
    float s0[4];      // odd oj, pixel 0
    float s7[4];      // odd oj, pixel 7
    #pragma unroll
    for (int e = 0; e < 5; ++e)
        #pragma unroll
        for (int p = 0; p < 4; ++p) ae[e][p] = 0ull;
    #pragma unroll
    for (int o = 0; o < 4; ++o) {
        s0[o] = 0.f; s7[o] = 0.f;
        #pragma unroll
        for (int p = 0; p < 3; ++p) ao[o][p] = 0ull;
    }

    const float4 z4 = make_float4(0.f, 0.f, 0.f, 0.f);

    #pragma unroll 1
    for (int c = 0; c < CH; ++c, xp += NPIX, yp += NPIX) {
        // All 6 loads up front; warp parallelism (4.6 warps/SMSP) hides latency.
        const float4 xa = *(const float4*)xp;
        const float4 xb = *(const float4*)(xp + 4);
        const float4 y0 = first ? z4 : *(const float4*)yp;          // j0-4..j0-1
        const float4 y1 = *(const float4*)(yp + 4);                 // j0..j0+3
        const float4 y2 = *(const float4*)(yp + 8);                 // j0+4..j0+7
        const float4 y3 = last  ? z4 : *(const float4*)(yp + 12);   // j0+8..j0+11

        u64 ypr[8];
        ypr[0] = pk2(y0.x, y0.y); ypr[1] = pk2(y0.z, y0.w);
        ypr[2] = pk2(y1.x, y1.y); ypr[3] = pk2(y1.z, y1.w);
        ypr[4] = pk2(y2.x, y2.y); ypr[5] = pk2(y2.z, y2.w);
        ypr[6] = pk2(y3.x, y3.y); ypr[7] = pk2(y3.z, y3.w);
        u64 xe[4];
        xe[0] = pk2(xa.x, xa.y); xe[1] = pk2(xa.z, xa.w);
        xe[2] = pk2(xb.x, xb.y); xe[3] = pk2(xb.z, xb.w);
        u64 xo[3];
        xo[0] = pk2(xa.y, xa.z); xo[1] = pk2(xa.w, xb.x);
        xo[2] = pk2(xb.y, xb.z);

        #pragma unroll
        for (int e = 0; e < 5; ++e)
            #pragma unroll
            for (int p = 0; p < 4; ++p) ffma2(ae[e][p], xe[p], ypr[p + e]);
        #pragma unroll
        for (int o = 0; o < 4; ++o)
            #pragma unroll
            for (int p = 0; p < 3; ++p) ffma2(ao[o][p], xo[p], ypr[p + o + 1]);

        s0[0] = fmaf(xa.x, y0.y, s0[0]);
        s0[1] = fmaf(xa.x, y0.w, s0[1]);
        s0[2] = fmaf(xa.x, y1.y, s0[2]);
        s0[3] = fmaf(xa.x, y1.w, s0[3]);
        s7[0] = fmaf(xb.w, y2.x, s7[0]);
        s7[1] = fmaf(xb.w, y2.z, s7[1]);
        s7[2] = fmaf(xb.w, y3.x, s7[2]);
        s7[3] = fmaf(xb.w, y3.z, s7[3]);
    }

    const float sc = 1.0f / (float)CH;

    // Even oj = 2e
    #pragma unroll
    for (int e = 0; e < 5; ++e) {
        float v[8];
        #pragma unroll
        for (int p = 0; p < 4; ++p) upk2(ae[e][p], v[2 * p], v[2 * p + 1]);
        float* op = outp + (2 * e) * NPIX;
        *(float4*)op       = make_float4(v[0] * sc, v[1] * sc, v[2] * sc, v[3] * sc);
        *(float4*)(op + 4) = make_float4(v[4] * sc, v[5] * sc, v[6] * sc, v[7] * sc);
    }
    // Odd oj = 2o+1
    #pragma unroll
    for (int o = 0; o < 4; ++o) {
        float v[8];
        v[0] = s0[o];
        #pragma unroll
        for (int p = 0; p < 3; ++p) upk2(ao[o][p], v[2 * p + 1], v[2 * p + 2]);
        v[7] = s7[o];
        float* op = outp + (2 * o + 1) * NPIX;
        *(float4*)op       = make_float4(v[0] * sc, v[1] * sc, v[2] * sc, v[3] * sc);
        *(float4*)(op + 4) = make_float4(v[4] * sc, v[5] * sc, v[6] * sc, v[7] * sc);
    }
}

extern "C" void kernel_launch(void* const* d_in, const int* in_sizes, int n_in,
                              void* d_out, int out_size) {
    const float* x = (const float*)d_in[0];
    const float* y = (const float*)d_in[1];
    float* out = (float*)d_out;
    dim3 grid(HH / 2, BATCH);
    corr_kernel<<<grid, 144>>>(x, y, out);
}

// round 5
// speedup vs baseline: 1.1067x; 1.1067x over previous
#include <cuda_runtime.h>

#define BATCH 16
#define CH    256
#define HW    64
#define NPIX  (HW * HW)

typedef unsigned long long u64;

__device__ __forceinline__ u64 pk2(float lo, float hi) {
    u64 r;
    asm("mov.b64 %0, {%1, %2};" : "=l"(r) : "f"(lo), "f"(hi));
    return r;
}
__device__ __forceinline__ void upk2(u64 v, float &lo, float &hi) {
    asm("mov.b64 {%0, %1}, %2;" : "=f"(lo), "=f"(hi) : "l"(v));
}
__device__ __forceinline__ void ffma2(u64 &d, u64 a, u64 b) {
    asm("fma.rn.f32x2 %0, %1, %2, %0;" : "+l"(d) : "l"(a), "l"(b));
}

// out[b, oi*9+oj, i, j] = (1/C) * sum_c x[b,c,i,j] * y[b,c,i+oi-4, j+oj-4]
//
// Block: 288 thr = 9 warps (warp = oi), covers b = blockIdx.y, rows i0..i0+3.
// Lane: jg = l&7 (j0 = 8*jg), ro = l>>3 (row i0+ro); 8 px * 9 oj accumulators.
// smem: double buffer; per channel 16 rows (12 y: i0-4..i0+7, 4 x: i0..i0+3),
// each row = 18 float4 chunks: [zero-guard | 16 data swizzled by chunk^(row&3) | zero-guard].
// Guards absorb the j<0 / j>63 window zero-padding; OOB y rows loaded as zeros.
__global__ __launch_bounds__(288, 2)
void corr_kernel(const float* __restrict__ x, const float* __restrict__ y,
                 float* __restrict__ out) {
    __shared__ float4 sm[2][16][18];

    const int tid = threadIdx.x;
    const int b   = blockIdx.y;
    const int i0  = blockIdx.x * 4;

    // ---- zero the guard chunks once (both buffers) ----
    if (tid < 64) {
        const int bf = tid >> 5, row = (tid >> 1) & 15, g = tid & 1;
        sm[bf][row][g * 17] = make_float4(0.f, 0.f, 0.f, 0.f);
    }

    // ---- cooperative loader setup (tid < 256) ----
    const bool isload = tid < 256;
    const int  lrow = tid >> 4;       // local row 0..15
    const int  lck  = tid & 15;       // chunk 0..15
    const bool isx  = lrow >= 12;
    int grow = isx ? (i0 + lrow - 12) : (i0 - 4 + lrow);
    const bool valid = isx || ((unsigned)grow < (unsigned)HW);
    if (!valid) grow = 0;
    const float* gsrc = (isx ? x : y)
                      + (size_t)b * CH * NPIX + grow * HW + lck * 4;
    const int dck = 1 + (lck ^ (lrow & 3));

    // ---- prologue: stage channel 0 into buffer 0 ----
    {
        float4 v = make_float4(0.f, 0.f, 0.f, 0.f);
        if (isload && valid) v = *(const float4*)gsrc;
        if (isload) sm[0][lrow][dck] = v;
    }
    __syncthreads();

    // ---- compute-lane constants ----
    const int lane = tid & 31;
    const int jg   = lane & 7;        // j0 = 8*jg
    const int ro   = lane >> 3;       // output row i0+ro
    const int oi   = tid >> 5;        // 0..8
    const int srow = ro + oi;         // y row index in smem (0..11)
    const int s    = srow & 3;
    const int m0 = 2 * jg - 1, m3 = 2 * jg + 2;
    const int yc0 = (m0 < 0) ? 0 : (1 + (m0 ^ s));
    const int yc1 = 1 + ((2 * jg)     ^ s);
    const int yc2 = 1 + ((2 * jg + 1) ^ s);
    const int yc3 = (m3 > 15) ? 17 : (1 + (m3 ^ s));
    const int xrow = 12 + ro;
    const int sx   = ro & 3;          // (12+ro)&3
    const int xc0  = 1 + ((2 * jg)     ^ sx);
    const int xc1  = 1 + ((2 * jg + 1) ^ sx);

    u64 aE[5][4], aO[4][4];
    #pragma unroll
    for (int e = 0; e < 5; ++e)
        #pragma unroll
        for (int t = 0; t < 4; ++t) aE[e][t] = 0ull;
    #pragma unroll
    for (int o = 0; o < 4; ++o)
        #pragma unroll
        for (int t = 0; t < 4; ++t) aO[o][t] = 0ull;

    const float* gnext = gsrc + NPIX;

    #pragma unroll 1
    for (int c = 0; c < CH; ++c) {
        // prefetch channel c+1 (issues early; consumed by STS at loop bottom)
        float4 pf = make_float4(0.f, 0.f, 0.f, 0.f);
        if (isload && valid && (c + 1 < CH)) pf = *(const float4*)gnext;

        const int pc = c & 1;
        // y window w[-4..11] for this lane's row/j-group
        const float4 v0 = sm[pc][srow][yc0];
        const float4 v1 = sm[pc][srow][yc1];
        const float4 v2 = sm[pc][srow][yc2];
        const float4 v3 = sm[pc][srow][yc3];
        const float4 xv0 = sm[pc][xrow][xc0];
        const float4 xv1 = sm[pc][xrow][xc1];

        u64 X[4];
        X[0] = pk2(xv0.x, xv0.y); X[1] = pk2(xv0.z, xv0.w);
        X[2] = pk2(xv1.x, xv1.y); X[3] = pk2(xv1.z, xv1.w);

        u64 E[8];   // even-aligned y pairs (w[-4+2e], w[-3+2e])
        E[0] = pk2(v0.x, v0.y); E[1] = pk2(v0.z, v0.w);
        E[2] = pk2(v1.x, v1.y); E[3] = pk2(v1.z, v1.w);
        E[4] = pk2(v2.x, v2.y); E[5] = pk2(v2.z, v2.w);
        E[6] = pk2(v3.x, v3.y); E[7] = pk2(v3.z, v3.w);

        u64 O[7];   // odd-aligned y pairs (w[-3+2o], w[-2+2o])
        O[0] = pk2(v0.y, v0.z); O[1] = pk2(v0.w, v1.x);
        O[2] = pk2(v1.y, v1.z); O[3] = pk2(v1.w, v2.x);
        O[4] = pk2(v2.y, v2.z); O[5] = pk2(v2.w, v3.x);
        O[6] = pk2(v3.y, v3.z);

        #pragma unroll
        for (int e = 0; e < 5; ++e)          // even oj = 2e
            #pragma unroll
            for (int t = 0; t < 4; ++t) ffma2(aE[e][t], X[t], E[e + t]);
        #pragma unroll
        for (int o = 0; o < 4; ++o)          // odd oj = 2o+1
            #pragma unroll
            for (int t = 0; t < 4; ++t) ffma2(aO[o][t], X[t], O[o + t]);

        if (isload) sm[pc ^ 1][lrow][dck] = pf;
        __syncthreads();
        gnext += NPIX;
    }

    // ---- epilogue ----
    const float sc = 1.0f / (float)CH;
    float* ob = out + (((size_t)b * 81 + (size_t)oi * 9) * HW + (i0 + ro)) * HW
                    + 8 * jg;
    #pragma unroll
    for (int e = 0; e < 5; ++e) {            // oj = 2e
        float v[8];
        #pragma unroll
        for (int t = 0; t < 4; ++t) upk2(aE[e][t], v[2 * t], v[2 * t + 1]);
        float* op = ob + (size_t)(2 * e) * NPIX;
        *(float4*)op       = make_float4(v[0] * sc, v[1] * sc, v[2] * sc, v[3] * sc);
        *(float4*)(op + 4) = make_float4(v[4] * sc, v[5] * sc, v[6] * sc, v[7] * sc);
    }
    #pragma unroll
    for (int o = 0; o < 4; ++o) {            // oj = 2o+1
        float v[8];
        #pragma unroll
        for (int t = 0; t < 4; ++t) upk2(aO[o][t], v[2 * t], v[2 * t + 1]);
        float* op = ob + (size_t)(2 * o + 1) * NPIX;
        *(float4*)op       = make_float4(v[0] * sc, v[1] * sc, v[2] * sc, v[3] * sc);
        *(float4*)(op + 4) = make_float4(v[4] * sc, v[5] * sc, v[6] * sc, v[7] * sc);
    }
}

extern "C" void kernel_launch(void* const* d_in, const int* in_sizes, int n_in,
                              void* d_out, int out_size) {
    const float* x = (const float*)d_in[0];
    const float* y = (const float*)d_in[1];
    float* out = (float*)d_out;
    dim3 grid(HW / 4, BATCH);   // (16 row-groups, 16 batches)
    corr_kernel<<<grid, 288>>>(x, y, out);
}

// round 6
// speedup vs baseline: 1.2461x; 1.1260x over previous
#include <cuda_runtime.h>
#include <cstdint>

#define BATCH 16
#define CH    256
#define HW    64
#define NPIX  (HW * HW)

#define STAGES 8          // ring depth (power of 2)
#define PDIST  7          // prefetch distance

typedef unsigned long long u64;

__device__ __forceinline__ u64 pk2(float lo, float hi) {
    u64 r;
    asm("mov.b64 %0, {%1, %2};" : "=l"(r) : "f"(lo), "f"(hi));
    return r;
}
__device__ __forceinline__ void upk2(u64 v, float &lo, float &hi) {
    asm("mov.b64 {%0, %1}, %2;" : "=f"(lo), "=f"(hi) : "l"(v));
}
__device__ __forceinline__ void ffma2(u64 &d, u64 a, u64 b) {
    asm("fma.rn.f32x2 %0, %1, %2, %0;" : "+l"(d) : "l"(a), "l"(b));
}
// 16B async copy, zero-fill when srcsz==0 (LDGSTS, L2-only path)
__device__ __forceinline__ void cp16z(uint32_t dst, const float* src, int srcsz) {
    asm volatile("cp.async.cg.shared.global [%0], [%1], 16, %2;"
                 :: "r"(dst), "l"(src), "r"(srcsz));
}
__device__ __forceinline__ void cp_commit() {
    asm volatile("cp.async.commit_group;");
}

// out[b, oi*9+oj, i, j] = (1/C) * sum_c x[b,c,i,j] * y[b,c,i+oi-4, j+oj-4]
// Block: 288 thr = 9 warps (warp = oi), covers b, output rows i0..i0+3.
// smem ring: STAGES x 16 rows (12 y rows i0-4..i0+7, 4 x rows i0..i0+3),
// row = 18 float4 chunks [guard | 16 data, chunk^(row&3) swizzle | guard].
// cp.async keeps PDIST channels in flight -> DRAM latency amortized.
__global__ __launch_bounds__(288, 2)
void corr_kernel(const float* __restrict__ x, const float* __restrict__ y,
                 float* __restrict__ out) {
    __shared__ float4 sm[STAGES][16][18];

    const int tid = threadIdx.x;
    const int b   = blockIdx.y;
    const int i0  = blockIdx.x * 4;

    // zero guard chunks in all stages (never overwritten afterwards)
    if (tid < 256) {
        const int st = tid >> 5, row = (tid >> 1) & 15, g = tid & 1;
        sm[st][row][g * 17] = make_float4(0.f, 0.f, 0.f, 0.f);
    }

    // ---- cooperative loader setup (one 16B chunk per thread, tid < 256) ----
    const bool isload = tid < 256;
    const int  lrow = (tid >> 4) & 15;    // local row 0..15
    const int  lck  = tid & 15;           // chunk 0..15
    const bool isx  = lrow >= 12;
    int grow = isx ? (i0 + lrow - 12) : (i0 - 4 + lrow);
    const bool valid = isx || ((unsigned)grow < (unsigned)HW);
    if (!valid) grow = 0;
    const float* gsrc = (isx ? x : y) + (size_t)b * CH * NPIX + grow * HW + lck * 4;
    const int dck   = 1 + (lck ^ (lrow & 3));
    const int srcsz = valid ? 16 : 0;
    const uint32_t stage_b = 16 * 18 * 16;     // bytes per stage
    const uint32_t sdst = (uint32_t)__cvta_generic_to_shared(&sm[0][lrow][dck]);

    // ---- prologue: launch channels 0..PDIST-1 ----
    #pragma unroll
    for (int c = 0; c < PDIST; ++c) {
        if (isload) cp16z(sdst + (uint32_t)c * stage_b, gsrc + (size_t)c * NPIX, srcsz);
        cp_commit();
    }

    // ---- compute-lane constants ----
    const int lane = tid & 31;
    const int jg   = lane & 7;        // j0 = 8*jg
    const int ro   = lane >> 3;       // output row i0+ro
    const int oi   = tid >> 5;        // 0..8
    const int srow = ro + oi;         // y row in smem (0..11)
    const int s    = srow & 3;
    const int m0 = 2 * jg - 1, m3 = 2 * jg + 2;
    const int yc0 = (m0 < 0) ? 0 : (1 + (m0 ^ s));
    const int yc1 = 1 + ((2 * jg)     ^ s);
    const int yc2 = 1 + ((2 * jg + 1) ^ s);
    const int yc3 = (m3 > 15) ? 17 : (1 + (m3 ^ s));
    const int xrow = 12 + ro;
    const int sx   = ro & 3;
    const int xc0  = 1 + ((2 * jg)     ^ sx);
    const int xc1  = 1 + ((2 * jg + 1) ^ sx);

    u64 aE[5][4], aO[4][4];
    #pragma unroll
    for (int e = 0; e < 5; ++e)
        #pragma unroll
        for (int t = 0; t < 4; ++t) aE[e][t] = 0ull;
    #pragma unroll
    for (int o = 0; o < 4; ++o)
        #pragma unroll
        for (int t = 0; t < 4; ++t) aO[o][t] = 0ull;

    const float* gpre = gsrc + (size_t)PDIST * NPIX;

    #pragma unroll 1
    for (int c = 0; c < CH; ++c) {
        // my copies for channel c are done; barrier makes everyone's visible
        asm volatile("cp.async.wait_group %0;" :: "n"(PDIST - 1));
        __syncthreads();

        const int st = c & (STAGES - 1);
        const float4 v0  = sm[st][srow][yc0];
        const float4 v1  = sm[st][srow][yc1];
        const float4 v2  = sm[st][srow][yc2];
        const float4 v3  = sm[st][srow][yc3];
        const float4 xv0 = sm[st][xrow][xc0];
        const float4 xv1 = sm[st][xrow][xc1];

        u64 X[4];
        X[0] = pk2(xv0.x, xv0.y); X[1] = pk2(xv0.z, xv0.w);
        X[2] = pk2(xv1.x, xv1.y); X[3] = pk2(xv1.z, xv1.w);

        u64 E[8];   // even-aligned y pairs
        E[0] = pk2(v0.x, v0.y); E[1] = pk2(v0.z, v0.w);
        E[2] = pk2(v1.x, v1.y); E[3] = pk2(v1.z, v1.w);
        E[4] = pk2(v2.x, v2.y); E[5] = pk2(v2.z, v2.w);
        E[6] = pk2(v3.x, v3.y); E[7] = pk2(v3.z, v3.w);
        u64 O[7];   // odd-aligned y pairs
        O[0] = pk2(v0.y, v0.z); O[1] = pk2(v0.w, v1.x);
        O[2] = pk2(v1.y, v1.z); O[3] = pk2(v1.w, v2.x);
        O[4] = pk2(v2.y, v2.z); O[5] = pk2(v2.w, v3.x);
        O[6] = pk2(v3.y, v3.z);

        #pragma unroll
        for (int e = 0; e < 5; ++e)          // even oj = 2e
            #pragma unroll
            for (int t = 0; t < 4; ++t) ffma2(aE[e][t], X[t], E[e + t]);
        #pragma unroll
        for (int o = 0; o < 4; ++o)          // odd oj = 2o+1
            #pragma unroll
            for (int t = 0; t < 4; ++t) ffma2(aO[o][t], X[t], O[o + t]);

        // refill stage (c+PDIST)&7 == (c-1)&7: safe, everyone passed the barrier
        if (isload && (c + PDIST < CH))
            cp16z(sdst + (uint32_t)((c + PDIST) & (STAGES - 1)) * stage_b, gpre, srcsz);
        cp_commit();
        gpre += NPIX;
    }

    // ---- epilogue ----
    const float sc = 1.0f / (float)CH;
    float* ob = out + (((size_t)b * 81 + (size_t)oi * 9) * HW + (i0 + ro)) * HW
                    + 8 * jg;
    #pragma unroll
    for (int e = 0; e < 5; ++e) {            // oj = 2e
        float v[8];
        #pragma unroll
        for (int t = 0; t < 4; ++t) upk2(aE[e][t], v[2 * t], v[2 * t + 1]);
        float* op = ob + (size_t)(2 * e) * NPIX;
        *(float4*)op       = make_float4(v[0] * sc, v[1] * sc, v[2] * sc, v[3] * sc);
        *(float4*)(op + 4) = make_float4(v[4] * sc, v[5] * sc, v[6] * sc, v[7] * sc);
    }
    #pragma unroll
    for (int o = 0; o < 4; ++o) {            // oj = 2o+1
        float v[8];
        #pragma unroll
        for (int t = 0; t < 4; ++t) upk2(aO[o][t], v[2 * t], v[2 * t + 1]);
        float* op = ob + (size_t)(2 * o + 1) * NPIX;
        *(float4*)op       = make_float4(v[0] * sc, v[1] * sc, v[2] * sc, v[3] * sc);
        *(float4*)(op + 4) = make_float4(v[4] * sc, v[5] * sc, v[6] * sc, v[7] * sc);
    }
}

extern "C" void kernel_launch(void* const* d_in, const int* in_sizes, int n_in,
                              void* d_out, int out_size) {
    const float* x = (const float*)d_in[0];
    const float* y = (const float*)d_in[1];
    float* out = (float*)d_out;
    dim3 grid(HW / 4, BATCH);   // 16 row-groups x 16 batches = 256 blocks
    corr_kernel<<<grid, 288>>>(x, y, out);
}

// round 8
// speedup vs baseline: 1.4166x; 1.1368x over previous
#include <cuda_runtime.h>
#include <cstdint>

#define BATCH 16
#define CH    256
#define HW    64
#define NPIX  (HW * HW)
#define STAGES 8          // ring depth (4 groups x 2 channels)

typedef unsigned long long u64;

__device__ __forceinline__ u64 pk2(float lo, float hi) {
    u64 r;
    asm("mov.b64 %0, {%1, %2};" : "=l"(r) : "f"(lo), "f"(hi));
    return r;
}
__device__ __forceinline__ void upk2(u64 v, float &lo, float &hi) {
    asm("mov.b64 {%0, %1}, %2;" : "=f"(lo), "=f"(hi) : "l"(v));
}
__device__ __forceinline__ void ffma2(u64 &d, u64 a, u64 b) {
    asm("fma.rn.f32x2 %0, %1, %2, %0;" : "+l"(d) : "l"(a), "l"(b));
}
__device__ __forceinline__ void cp16z(uint32_t dst, const float* src, int srcsz) {
    asm volatile("cp.async.cg.shared.global [%0], [%1], 16, %2;"
                 :: "r"(dst), "l"(src), "r"(srcsz));
}
__device__ __forceinline__ void cp_commit() {
    asm volatile("cp.async.commit_group;");
}

// slot permutation: data chunk c (0..15) -> slot 1+c+(c>>3) in {1..8,10..17};
// slot 9 = shared zero guard (covers window chunk -1 and 16); slot 0 unused.
// Per quarter-warp phase, all access classes hit 8 distinct bank-quads mod 8.
#define SLOT(c) (1 + (c) + ((c) >> 3))

// out[b, oi*9+oj, i, j] = (1/C) * sum_c x[b,c,i,j] * y[b,c,i+oi-4, j+oj-4]
// Block: 288 thr = 9 warps (warp = oi), covers b, output rows i0..i0+3.
// smem ring: STAGES x 16 rows (12 y rows i0-4..i0+7, 4 x rows i0..i0+3) x 18 slots.
__global__ __launch_bounds__(288, 2)
void corr_kernel(const float* __restrict__ x, const float* __restrict__ y,
                 float* __restrict__ out) {
    __shared__ float4 sm[STAGES][16][18];

    const int tid = threadIdx.x;
    const int b   = blockIdx.y;
    const int i0  = blockIdx.x * 4;

    // zero the shared guard slot (slot 9) in all stages/rows
    if (tid < 128) sm[tid >> 4][tid & 15][9] = make_float4(0.f, 0.f, 0.f, 0.f);

    // ---- cooperative loader setup (one 16B chunk per thread, tid < 256) ----
    const bool isload = tid < 256;
    const int  lrow = (tid >> 4) & 15;    // local row 0..15
    const int  lck  = tid & 15;           // data chunk 0..15
    const bool isx  = lrow >= 12;
    int grow = isx ? (i0 + lrow - 12) : (i0 - 4 + lrow);
    const bool valid = isx || ((unsigned)grow < (unsigned)HW);
    if (!valid) grow = 0;
    const float* gsrc = (isx ? x : y) + (size_t)b * CH * NPIX + grow * HW + lck * 4;
    const int srcsz = valid ? 16 : 0;
    const uint32_t stage_b = 16 * 18 * 16;     // bytes per stage
    const uint32_t sdst =
        (uint32_t)__cvta_generic_to_shared(&sm[0][lrow][SLOT(lck)]);

    // ---- prologue: 3 groups x 2 channels (ch 0..5 in flight) ----
    #pragma unroll
    for (int g = 0; g < 3; ++g) {
        if (isload) {
            cp16z(sdst + (uint32_t)(2 * g)     * stage_b, gsrc + (size_t)(2 * g)     * NPIX, srcsz);
            cp16z(sdst + (uint32_t)(2 * g + 1) * stage_b, gsrc + (size_t)(2 * g + 1) * NPIX, srcsz);
        }
        cp_commit();
    }

    // ---- compute-lane constants ----
    const int lane = tid & 31;
    const int jg   = lane & 7;        // j0 = 8*jg
    const int ro   = lane >> 3;       // output row i0+ro
    const int oi   = tid >> 5;        // 0..8
    const int srow = ro + oi;         // y row in smem (0..11)
    const int yc0  = (jg == 0) ? 9 : SLOT(2 * jg - 1);
    const int yc1  = SLOT(2 * jg);
    const int yc2  = SLOT(2 * jg + 1);
    const int yc3  = (jg == 7) ? 9 : SLOT(2 * jg + 2);
    const int xrow = 12 + ro;

    u64 aE[5][4], aO[4][4];
    #pragma unroll
    for (int e = 0; e < 5; ++e)
        #pragma unroll
        for (int t = 0; t < 4; ++t) aE[e][t] = 0ull;
    #pragma unroll
    for (int o = 0; o < 4; ++o)
        #pragma unroll
        for (int t = 0; t < 4; ++t) aO[o][t] = 0ull;

#define COMPUTE_CH(st)                                                         \
    {                                                                          \
        const float4 v0  = sm[st][srow][yc0];                                  \
        const float4 v1  = sm[st][srow][yc1];                                  \
        const float4 v2  = sm[st][srow][yc2];                                  \
        const float4 v3  = sm[st][srow][yc3];                                  \
        const float4 xv0 = sm[st][xrow][yc1];                                  \
        const float4 xv1 = sm[st][xrow][yc2];                                  \
        u64 X[4];                                                              \
        X[0] = pk2(xv0.x, xv0.y); X[1] = pk2(xv0.z, xv0.w);                    \
        X[2] = pk2(xv1.x, xv1.y); X[3] = pk2(xv1.z, xv1.w);                    \
        u64 E[8];                                                              \
        E[0] = pk2(v0.x, v0.y); E[1] = pk2(v0.z, v0.w);                        \
        E[2] = pk2(v1.x, v1.y); E[3] = pk2(v1.z, v1.w);                        \
        E[4] = pk2(v2.x, v2.y); E[5] = pk2(v2.z, v2.w);                        \
        E[6] = pk2(v3.x, v3.y); E[7] = pk2(v3.z, v3.w);                        \
        u64 O[7];                                                              \
        O[0] = pk2(v0.y, v0.z); O[1] = pk2(v0.w, v1.x);                        \
        O[2] = pk2(v1.y, v1.z); O[3] = pk2(v1.w, v2.x);                        \
        O[4] = pk2(v2.y, v2.z); O[5] = pk2(v2.w, v3.x);                        \
        O[6] = pk2(v3.y, v3.z);                                                \
        _Pragma("unroll")                                                      \
        for (int e = 0; e < 5; ++e)                                            \
            _Pragma("unroll")                                                  \
            for (int t = 0; t < 4; ++t) ffma2(aE[e][t], X[t], E[e + t]);       \
        _Pragma("unroll")                                                      \
        for (int o = 0; o < 4; ++o)                                            \
            _Pragma("unroll")                                                  \
            for (int t = 0; t < 4; ++t) ffma2(aO[o][t], X[t], O[o + t]);       \
    }

    const float* gpre = gsrc + (size_t)6 * NPIX;

    #pragma unroll 1
    for (int k = 0; k < CH / 2; ++k) {
        // group k (channels 2k, 2k+1) complete; barrier publishes to all warps
        asm volatile("cp.async.wait_group 2;" ::: "memory");
        __syncthreads();

        const int st0 = (2 * k) & (STAGES - 1);
        COMPUTE_CH(st0);
        COMPUTE_CH(st0 + 1);          // (2k+1)&7 == st0+1 (st0 is even)

        // refill stages (2k+6)&7, (2k+7)&7 (consumed in iter k-1; safe)
        if (isload && (2 * k + 6 < CH)) {
            cp16z(sdst + (uint32_t)((2 * k + 6) & (STAGES - 1)) * stage_b, gpre, srcsz);
            cp16z(sdst + (uint32_t)((2 * k + 7) & (STAGES - 1)) * stage_b, gpre + NPIX, srcsz);
        }
        cp_commit();
        gpre += 2 * NPIX;
    }
#undef COMPUTE_CH

    // ---- epilogue ----
    const float sc = 1.0f / (float)CH;
    float* ob = out + (((size_t)b * 81 + (size_t)oi * 9) * HW + (i0 + ro)) * HW
                    + 8 * jg;
    #pragma unroll
    for (int e = 0; e < 5; ++e) {            // oj = 2e
        float v[8];
        #pragma unroll
        for (int t = 0; t < 4; ++t) upk2(aE[e][t], v[2 * t], v[2 * t + 1]);
        float* op = ob + (size_t)(2 * e) * NPIX;
        *(float4*)op       = make_float4(v[0] * sc, v[1] * sc, v[2] * sc, v[3] * sc);
        *(float4*)(op + 4) = make_float4(v[4] * sc, v[5] * sc, v[6] * sc, v[7] * sc);
    }
    #pragma unroll
    for (int o = 0; o < 4; ++o) {            // oj = 2o+1
        float v[8];
        #pragma unroll
        for (int t = 0; t < 4; ++t) upk2(aO[o][t], v[2 * t], v[2 * t + 1]);
        float* op = ob + (size_t)(2 * o + 1) * NPIX;
        *(float4*)op       = make_float4(v[0] * sc, v[1] * sc, v[2] * sc, v[3] * sc);
        *(float4*)(op + 4) = make_float4(v[4] * sc, v[5] * sc, v[6] * sc, v[7] * sc);
    }
}

extern "C" void kernel_launch(void* const* d_in, const int* in_sizes, int n_in,
                              void* d_out, int out_size) {
    const float* x = (const float*)d_in[0];
    const float* y = (const float*)d_in[1];
    float* out = (float*)d_out;
    dim3 grid(HW / 4, BATCH);   // 16 row-groups x 16 batches = 256 blocks
    corr_kernel<<<grid, 288>>>(x, y, out);
}